// round 8
// baseline (speedup 1.0000x reference)
#include <cuda_runtime.h>
#include <cuda_fp16.h>
#include <math.h>
#include <stdint.h>

#define Bb 4
#define Ss 4096
#define Dd 1024
#define Mm (Bb*Ss)       // 16384
#define NCHUNK 64
#define CLEN (Ss/NCHUNK) // 64

#define BM 128
#define BN 128
#define BK 32
#define NITER (Dd/BK)        // 32
#define NSTAGE 3

// fused (A + W0 + W1) stage, single-GEMM (A + W) stage
#define STAGE_F 24576
#define STAGE_S 16384
#define SMEM_F (NSTAGE*STAGE_F)   // 72KB
#define SMEM_S (NSTAGE*STAGE_S)   // 48KB

// ---------------- scratch (device globals) ----------------
__device__ float g_gate[(size_t)Mm*Dd];
__device__ float g_inp[(size_t)Mm*Dd];
__device__ float g_Ac[Bb*NCHUNK*Dd];
__device__ float g_Bc[Bb*NCHUNK*Dd];
__device__ float g_carry[Bb*NCHUNK*Dd];

__device__ __align__(16) __half g_x16[(size_t)Mm*Dd];
__device__ __align__(16) __half g_h16[(size_t)Mm*Dd];
__device__ __align__(16) __half g_w16[3][(size_t)Dd*Dd];

// ---------------- asm helpers (portable sm_80-era only) ----------------
__device__ __forceinline__ uint32_t smem_u32(const void* p) {
    uint32_t a;
    asm("{ .reg .u64 t; cvta.to.shared.u64 t, %1; cvt.u32.u64 %0, t; }" : "=r"(a) : "l"(p));
    return a;
}

#define CP_ASYNC16(s, g) \
    asm volatile("cp.async.cg.shared.global [%0], [%1], 16;" :: "r"(s), "l"(g))
#define CP_COMMIT() asm volatile("cp.async.commit_group;")
#define CP_WAIT1()  asm volatile("cp.async.wait_group 1;")
#define CP_WAIT0()  asm volatile("cp.async.wait_group 0;")

#define LDSM_X4(r0, r1, r2, r3, addr) \
    asm volatile("ldmatrix.sync.aligned.m8n8.x4.shared.b16 {%0,%1,%2,%3}, [%4];" \
        : "=r"(r0), "=r"(r1), "=r"(r2), "=r"(r3) : "r"(addr))

#define MMA_F16(c, a, b0, b1) \
    asm volatile("mma.sync.aligned.m16n8k16.row.col.f32.f16.f16.f32 " \
        "{%0,%1,%2,%3}, {%4,%5,%6,%7}, {%8,%9}, {%0,%1,%2,%3};" \
        : "+f"((c)[0]), "+f"((c)[1]), "+f"((c)[2]), "+f"((c)[3]) \
        : "r"((a)[0]), "r"((a)[1]), "r"((a)[2]), "r"((a)[3]), "r"(b0), "r"(b1))

__device__ __forceinline__ float softplusf(float v) {
    return (v > 20.0f) ? v : log1pf(expf(v));
}

// smem offset for (row, 16B-chunk c): 64B rows, XOR swizzle for conflict-free ldmatrix
__device__ __forceinline__ uint32_t swz(int row, int c) {
    return (uint32_t)(row * 64 + ((c ^ ((row >> 1) & 3)) << 4));
}

// ---------------- fp32 -> fp16 conversion ----------------
template<int DST>
__global__ void conv_f16(const float* __restrict__ src)
{
    size_t i = ((size_t)blockIdx.x * blockDim.x + threadIdx.x) * 8;
    __half* dst;
    if (DST == 0)      dst = g_x16;
    else if (DST == 1) dst = g_w16[0];
    else if (DST == 2) dst = g_w16[1];
    else               dst = g_w16[2];
    float4 v0 = *(const float4*)(src + i);
    float4 v1 = *(const float4*)(src + i + 4);
    __half2* d2 = (__half2*)(dst + i);
    d2[0] = __floats2half2_rn(v0.x, v0.y);
    d2[1] = __floats2half2_rn(v0.z, v0.w);
    d2[2] = __floats2half2_rn(v1.x, v1.y);
    d2[3] = __floats2half2_rn(v1.z, v1.w);
}

// ---------------- fused dt+B GEMM (two weight operands, one A pass) ----------------
// acc0 = x @ dt_w^T, acc1 = x @ B_w^T; epilogue: dt=softplus(acc0+dt_b),
// gate=exp(dt*-exp(A_log)), inp=dt*acc1*x (+gate*h0 at s=0). No dt array.
__global__ __launch_bounds__(512, 1)
void gemm_fused01(const float* __restrict__ dt_b, const float* __restrict__ A_log,
                  const float* __restrict__ h0,  const float* __restrict__ xptr)
{
    extern __shared__ char smem[];
    const __half* __restrict__ A  = g_x16;
    const __half* __restrict__ W0 = g_w16[0];
    const __half* __restrict__ W1 = g_w16[1];

    const int tid = threadIdx.x;
    const int wid = tid >> 5, lane = tid & 31;
    const int warpm = wid >> 3, warpn = wid & 7;      // 2 x 8 warps, 64x16 per warp
    const int bm = blockIdx.y * BM, bn = blockIdx.x * BN;
    const uint32_t sbase = smem_u32(smem);

    float acc0[4][2][4], acc1[4][2][4];
    #pragma unroll
    for (int a = 0; a < 4; a++)
        #pragma unroll
        for (int b = 0; b < 2; b++)
            #pragma unroll
            for (int c = 0; c < 4; c++) { acc0[a][b][c] = 0.0f; acc1[a][b][c] = 0.0f; }

    auto load_stage = [&](int s, int it) {
        uint32_t st = sbase + (uint32_t)s * STAGE_F;
        int k0 = it * BK;
        int row = tid >> 2, c = tid & 3;          // 512 threads = 128 rows x 4 chunks
        uint32_t soff = swz(row, c);
        size_t ga = (size_t)(bm + row) * Dd + k0 + c * 8;
        size_t gw = (size_t)(bn + row) * Dd + k0 + c * 8;
        CP_ASYNC16(st + soff,         A  + ga);
        CP_ASYNC16(st + 8192  + soff, W0 + gw);
        CP_ASYNC16(st + 16384 + soff, W1 + gw);
        CP_COMMIT();
    };

    load_stage(0, 0);
    load_stage(1, 1);

    for (int i = 0; i < NITER; i++) {
        if (i == NITER - 1) CP_WAIT0(); else CP_WAIT1();
        __syncthreads();
        if (i + 2 < NITER) load_stage((i + 2) % NSTAGE, i + 2);

        uint32_t st = sbase + (uint32_t)(i % NSTAGE) * STAGE_F;
        #pragma unroll
        for (int kk = 0; kk < 2; kk++) {       // two k16 steps per BK=32 stage
            uint32_t ah[4][4], b0[4], b1[4];
            // B frags: 16 rows x 2 k-chunks per weight
            {
                int row = warpn * 16 + (lane & 7) + (((lane >> 4) & 1) << 3);
                int c = kk * 2 + ((lane >> 3) & 1);
                LDSM_X4(b0[0], b0[1], b0[2], b0[3], st + 8192  + swz(row, c));
                LDSM_X4(b1[0], b1[1], b1[2], b1[3], st + 16384 + swz(row, c));
            }
            #pragma unroll
            for (int mi = 0; mi < 4; mi++) {
                int row = warpm * 64 + mi * 16 + (lane & 15);
                int c = kk * 2 + (lane >> 4);
                LDSM_X4(ah[mi][0], ah[mi][1], ah[mi][2], ah[mi][3], st + swz(row, c));
            }
            #pragma unroll
            for (int mi = 0; mi < 4; mi++) {
                MMA_F16(acc0[mi][0], ah[mi], b0[0], b0[1]);
                MMA_F16(acc0[mi][1], ah[mi], b0[2], b0[3]);
                MMA_F16(acc1[mi][0], ah[mi], b1[0], b1[1]);
                MMA_F16(acc1[mi][1], ah[mi], b1[2], b1[3]);
            }
        }
    }

    // ---------------- epilogue: dt -> gate/inp, no dt store ----------------
    const int mb0 = bm + warpm * 64;
    const int nb0 = bn + warpn * 16;
    #pragma unroll
    for (int mi = 0; mi < 4; mi++) {
        #pragma unroll
        for (int r = 0; r < 2; r++) {
            int m = mb0 + mi * 16 + (lane >> 2) + r * 8;
            size_t off = (size_t)m * Dd;
            #pragma unroll
            for (int ni = 0; ni < 2; ni++) {
                int n = nb0 + ni * 8 + (lane & 3) * 2;
                float d0 = acc0[mi][ni][r * 2], d1 = acc0[mi][ni][r * 2 + 1];
                float p0 = acc1[mi][ni][r * 2], p1 = acc1[mi][ni][r * 2 + 1];
                float2 bv  = *(const float2*)&dt_b[n];
                float2 al2 = *(const float2*)&A_log[n];
                float2 xv  = *(const float2*)&xptr[off + n];
                float2 dt, gv, iv;
                dt.x = softplusf(d0 + bv.x);
                dt.y = softplusf(d1 + bv.y);
                gv.x = expf(dt.x * (-expf(al2.x)));
                gv.y = expf(dt.y * (-expf(al2.y)));
                iv.x = dt.x * p0 * xv.x;
                iv.y = dt.y * p1 * xv.y;
                if ((m & (Ss - 1)) == 0) {
                    int b = m / Ss;
                    float2 h0v = *(const float2*)&h0[(size_t)b * Dd + n];
                    iv.x += gv.x * h0v.x;
                    iv.y += gv.y * h0v.y;
                }
                *(float2*)&g_gate[off + n] = gv;
                *(float2*)&g_inp[off + n] = iv;
            }
        }
    }
}

// ---------------- output GEMM: out = h @ C_w^T + Dp*x ----------------
__global__ __launch_bounds__(256, 2)
void gemm_out(float* __restrict__ out,
              const float* __restrict__ Dp, const float* __restrict__ xptr)
{
    extern __shared__ char smem[];
    const __half* __restrict__ A = g_h16;
    const __half* __restrict__ W = g_w16[2];

    const int tid = threadIdx.x;
    const int wid = tid >> 5, lane = tid & 31;
    const int warpm = wid >> 2, warpn = wid & 3;      // 2 x 4 warps, 64x32 per warp
    const int bm = blockIdx.y * BM, bn = blockIdx.x * BN;
    const uint32_t sbase = smem_u32(smem);

    float acc[4][4][4];
    #pragma unroll
    for (int a = 0; a < 4; a++)
        #pragma unroll
        for (int b = 0; b < 4; b++)
            #pragma unroll
            for (int c = 0; c < 4; c++) acc[a][b][c] = 0.0f;

    auto load_stage = [&](int s, int it) {
        uint32_t st = sbase + (uint32_t)s * STAGE_S;
        int k0 = it * BK;
        #pragma unroll
        for (int p = 0; p < 2; p++) {
            int lin = tid + p * 256;
            int row = lin >> 2, c = lin & 3;
            uint32_t soff = swz(row, c);
            size_t ga = (size_t)(bm + row) * Dd + k0 + c * 8;
            size_t gw = (size_t)(bn + row) * Dd + k0 + c * 8;
            CP_ASYNC16(st + soff,        A + ga);
            CP_ASYNC16(st + 8192 + soff, W + gw);
        }
        CP_COMMIT();
    };

    load_stage(0, 0);
    load_stage(1, 1);

    for (int i = 0; i < NITER; i++) {
        if (i == NITER - 1) CP_WAIT0(); else CP_WAIT1();
        __syncthreads();
        if (i + 2 < NITER) load_stage((i + 2) % NSTAGE, i + 2);

        uint32_t st = sbase + (uint32_t)(i % NSTAGE) * STAGE_S;
        #pragma unroll
        for (int kk = 0; kk < 2; kk++) {
            uint32_t ah[4][4], bh[2][4];
            #pragma unroll
            for (int mi = 0; mi < 4; mi++) {
                int row = warpm * 64 + mi * 16 + (lane & 15);
                int c = kk * 2 + (lane >> 4);
                LDSM_X4(ah[mi][0], ah[mi][1], ah[mi][2], ah[mi][3], st + swz(row, c));
            }
            #pragma unroll
            for (int pr = 0; pr < 2; pr++) {
                int row = warpn * 32 + pr * 16 + (lane & 7) + (((lane >> 4) & 1) << 3);
                int c = kk * 2 + ((lane >> 3) & 1);
                LDSM_X4(bh[pr][0], bh[pr][1], bh[pr][2], bh[pr][3], st + 8192 + swz(row, c));
            }
            #pragma unroll
            for (int mi = 0; mi < 4; mi++)
                #pragma unroll
                for (int ni = 0; ni < 4; ni++)
                    MMA_F16(acc[mi][ni], ah[mi], bh[ni >> 1][(ni & 1) * 2], bh[ni >> 1][(ni & 1) * 2 + 1]);
        }
    }

    const int mb0 = bm + warpm * 64;
    const int nb0 = bn + warpn * 32;
    #pragma unroll
    for (int mi = 0; mi < 4; mi++) {
        #pragma unroll
        for (int r = 0; r < 2; r++) {
            int m = mb0 + mi * 16 + (lane >> 2) + r * 8;
            size_t off = (size_t)m * Dd;
            #pragma unroll
            for (int ni = 0; ni < 4; ni++) {
                int n = nb0 + ni * 8 + (lane & 3) * 2;
                float v0 = acc[mi][ni][r * 2], v1 = acc[mi][ni][r * 2 + 1];
                float2 dp = *(const float2*)&Dp[n];
                float2 xv = *(const float2*)&xptr[off + n];
                float2 o;
                o.x = v0 + dp.x * xv.x;
                o.y = v1 + dp.y * xv.y;
                *(float2*)&out[off + n] = o;
            }
        }
    }
}

// ---------------- chunked associative scan ----------------
__global__ void scan_pass1()
{
    int idx = blockIdx.x * blockDim.x + threadIdx.x;
    int d = idx & (Dd - 1);
    int chunk = (idx / Dd) & (NCHUNK - 1);
    int b = idx / (Dd * NCHUNK);
    size_t base = ((size_t)b * Ss + (size_t)chunk * CLEN) * Dd + d;
    float a = 1.0f, h = 0.0f;
    #pragma unroll 8
    for (int t = 0; t < CLEN; t++) {
        float g  = g_gate[base + (size_t)t * Dd];
        float in = g_inp [base + (size_t)t * Dd];
        a *= g;
        h = g * h + in;
    }
    g_Ac[idx] = a;
    g_Bc[idx] = h;
}

__global__ void scan_pass2()
{
    int idx = blockIdx.x * blockDim.x + threadIdx.x;   // b*D + d
    int d = idx & (Dd - 1);
    int b = idx / Dd;
    const int base = b * NCHUNK * Dd + d;

    float A0[8], B0[8], A1[8], B1[8];
    #pragma unroll
    for (int j = 0; j < 8; j++) {
        A0[j] = g_Ac[base + j * Dd];
        B0[j] = g_Bc[base + j * Dd];
    }
    float c = 0.0f;
    #pragma unroll
    for (int ch = 0; ch < 8; ch++) {
        if (ch < 7) {
            #pragma unroll
            for (int j = 0; j < 8; j++) {
                A1[j] = g_Ac[base + ((ch + 1) * 8 + j) * Dd];
                B1[j] = g_Bc[base + ((ch + 1) * 8 + j) * Dd];
            }
        }
        #pragma unroll
        for (int j = 0; j < 8; j++) {
            g_carry[base + (ch * 8 + j) * Dd] = c;
            c = A0[j] * c + B0[j];
        }
        #pragma unroll
        for (int j = 0; j < 8; j++) { A0[j] = A1[j]; B0[j] = B1[j]; }
    }
}

__global__ void scan_pass3()
{
    int idx = blockIdx.x * blockDim.x + threadIdx.x;
    int d = idx & (Dd - 1);
    int chunk = (idx / Dd) & (NCHUNK - 1);
    int b = idx / (Dd * NCHUNK);
    size_t base = ((size_t)b * Ss + (size_t)chunk * CLEN) * Dd + d;
    float h = g_carry[idx];
    #pragma unroll 8
    for (int t = 0; t < CLEN; t++) {
        size_t o = base + (size_t)t * Dd;
        h = g_gate[o] * h + g_inp[o];
        g_h16[o] = __float2half(h);
    }
}

extern "C" void kernel_launch(void* const* d_in, const int* in_sizes, int n_in,
                              void* d_out, int out_size)
{
    const float* x     = (const float*)d_in[0];
    const float* h0    = (const float*)d_in[1];
    const float* dt_w  = (const float*)d_in[2];
    const float* dt_b  = (const float*)d_in[3];
    const float* A_log = (const float*)d_in[4];
    const float* B_w   = (const float*)d_in[5];
    const float* C_w   = (const float*)d_in[6];
    const float* Dp    = (const float*)d_in[7];
    float* out = (float*)d_out;

    cudaFuncSetAttribute(gemm_fused01, cudaFuncAttributeMaxDynamicSharedMemorySize, SMEM_F);
    cudaFuncSetAttribute(gemm_out,     cudaFuncAttributeMaxDynamicSharedMemorySize, SMEM_S);

    conv_f16<0><<<((size_t)Mm * Dd) / 2048, 256>>>(x);
    conv_f16<1><<<((size_t)Dd * Dd) / 2048, 256>>>(dt_w);
    conv_f16<2><<<((size_t)Dd * Dd) / 2048, 256>>>(B_w);
    conv_f16<3><<<((size_t)Dd * Dd) / 2048, 256>>>(C_w);

    dim3 grid(Dd / BN, Mm / BM);   // (8, 128)

    gemm_fused01<<<grid, 512, SMEM_F>>>(dt_b, A_log, h0, x);
    scan_pass1<<<(Bb * NCHUNK * Dd) / 256, 256>>>();
    scan_pass2<<<(Bb * Dd) / 256, 256>>>();
    scan_pass3<<<(Bb * NCHUNK * Dd) / 256, 256>>>();
    gemm_out<<<grid, 256, SMEM_S>>>(out, Dp, x);
}

// round 9
// speedup vs baseline: 1.1551x; 1.1551x over previous
#include <cuda_runtime.h>
#include <cuda_fp16.h>
#include <math.h>
#include <stdint.h>

#define Bb 4
#define Ss 4096
#define Dd 1024
#define Mm (Bb*Ss)       // 16384
#define NCHUNK 64
#define CLEN (Ss/NCHUNK) // 64

#define BM 128
#define BN 128
#define BK 32
#define NITER (Dd/BK)        // 32
#define STAGE_BYTES 16384    // A 8K | W 8K
#define NSTAGE 3
#define SMEM_DYN (NSTAGE*STAGE_BYTES)

// ---------------- scratch (device globals) ----------------
__device__ float g_Ac[Bb*NCHUNK*Dd];
__device__ float g_Bc[Bb*NCHUNK*Dd];
__device__ float g_carry[Bb*NCHUNK*Dd];

__device__ __align__(16) __half  g_dt16[(size_t)Mm*Dd];
__device__ __align__(16) __half2 g_gi[(size_t)Mm*Dd];     // .x=gate, .y=inp
__device__ __align__(16) __half  g_x16[(size_t)Mm*Dd];
__device__ __align__(16) __half  g_h16[(size_t)Mm*Dd];
__device__ __align__(16) __half  g_w16[3][(size_t)Dd*Dd];

// ---------------- asm helpers (portable sm_80-era only) ----------------
__device__ __forceinline__ uint32_t smem_u32(const void* p) {
    uint32_t a;
    asm("{ .reg .u64 t; cvta.to.shared.u64 t, %1; cvt.u32.u64 %0, t; }" : "=r"(a) : "l"(p));
    return a;
}

#define CP_ASYNC16(s, g) \
    asm volatile("cp.async.cg.shared.global [%0], [%1], 16;" :: "r"(s), "l"(g))
#define CP_COMMIT() asm volatile("cp.async.commit_group;")
#define CP_WAIT1()  asm volatile("cp.async.wait_group 1;")
#define CP_WAIT0()  asm volatile("cp.async.wait_group 0;")

#define LDSM_X4(r0, r1, r2, r3, addr) \
    asm volatile("ldmatrix.sync.aligned.m8n8.x4.shared.b16 {%0,%1,%2,%3}, [%4];" \
        : "=r"(r0), "=r"(r1), "=r"(r2), "=r"(r3) : "r"(addr))

#define MMA_F16(c, a, b0, b1) \
    asm volatile("mma.sync.aligned.m16n8k16.row.col.f32.f16.f16.f32 " \
        "{%0,%1,%2,%3}, {%4,%5,%6,%7}, {%8,%9}, {%0,%1,%2,%3};" \
        : "+f"((c)[0]), "+f"((c)[1]), "+f"((c)[2]), "+f"((c)[3]) \
        : "r"((a)[0]), "r"((a)[1]), "r"((a)[2]), "r"((a)[3]), "r"(b0), "r"(b1))

__device__ __forceinline__ float softplusf(float v) {
    return (v > 20.0f) ? v : log1pf(expf(v));
}

// smem offset for (row, 16B-chunk c): 64B rows, XOR swizzle for conflict-free ldmatrix
__device__ __forceinline__ uint32_t swz(int row, int c) {
    return (uint32_t)(row * 64 + ((c ^ ((row >> 1) & 3)) << 4));
}

// ---------------- fp32 -> fp16 conversions ----------------
__global__ void conv_x(const float* __restrict__ src)
{
    size_t i = ((size_t)blockIdx.x * blockDim.x + threadIdx.x) * 8;
    float4 v0 = *(const float4*)(src + i);
    float4 v1 = *(const float4*)(src + i + 4);
    __half2* d2 = (__half2*)(g_x16 + i);
    d2[0] = __floats2half2_rn(v0.x, v0.y);
    d2[1] = __floats2half2_rn(v0.z, v0.w);
    d2[2] = __floats2half2_rn(v1.x, v1.y);
    d2[3] = __floats2half2_rn(v1.z, v1.w);
}

__global__ void conv_w3(const float* __restrict__ w0, const float* __restrict__ w1,
                        const float* __restrict__ w2)
{
    int seg = blockIdx.y;
    const float* src = (seg == 0) ? w0 : (seg == 1) ? w1 : w2;
    __half* dst = g_w16[seg];
    size_t i = ((size_t)blockIdx.x * blockDim.x + threadIdx.x) * 8;
    float4 v0 = *(const float4*)(src + i);
    float4 v1 = *(const float4*)(src + i + 4);
    __half2* d2 = (__half2*)(dst + i);
    d2[0] = __floats2half2_rn(v0.x, v0.y);
    d2[1] = __floats2half2_rn(v0.z, v0.w);
    d2[2] = __floats2half2_rn(v1.x, v1.y);
    d2[3] = __floats2half2_rn(v1.z, v1.w);
}

// ---------------- fp16 single-pass tensor-core GEMM ----------------
// out[m,n] = sum_k A[m,k] * W[n,k]
// MODE 0: g_dt16 = softplus(acc + dt_b[n])       aux1 = dt_b
// MODE 1: gate/inp epilogue -> g_gi              aux2 = A_log, aux3 = h0, xptr = x
// MODE 2: out = acc + Dp[n]*x                    aux1 = Dp, xptr = x
template<int MODE>
__global__ __launch_bounds__(256, 2)
void gemm_f16(float* __restrict__ out,
              const float* __restrict__ aux1, const float* __restrict__ aux2,
              const float* __restrict__ aux3, const float* __restrict__ xptr)
{
    extern __shared__ char smem[];
    const __half* __restrict__ A = (MODE == 2) ? g_h16 : g_x16;
    const __half* __restrict__ W = g_w16[MODE];

    const int tid = threadIdx.x;
    const int wid = tid >> 5, lane = tid & 31;
    const int warpm = wid >> 2, warpn = wid & 3;      // 2 x 4 warps, 64x32 per warp
    const int bm = blockIdx.y * BM, bn = blockIdx.x * BN;
    const uint32_t sbase = smem_u32(smem);

    float acc[4][4][4];
    #pragma unroll
    for (int a = 0; a < 4; a++)
        #pragma unroll
        for (int b = 0; b < 4; b++)
            #pragma unroll
            for (int c = 0; c < 4; c++) acc[a][b][c] = 0.0f;

    auto load_stage = [&](int s, int it) {
        uint32_t st = sbase + (uint32_t)s * STAGE_BYTES;
        int k0 = it * BK;
        #pragma unroll
        for (int p = 0; p < 2; p++) {
            int lin = tid + p * 256;       // 0..511 chunks per array
            int row = lin >> 2, c = lin & 3;
            uint32_t soff = swz(row, c);
            size_t ga = (size_t)(bm + row) * Dd + k0 + c * 8;
            size_t gw = (size_t)(bn + row) * Dd + k0 + c * 8;
            CP_ASYNC16(st + soff,        A + ga);
            CP_ASYNC16(st + 8192 + soff, W + gw);
        }
        CP_COMMIT();
    };

    load_stage(0, 0);
    load_stage(1, 1);

    for (int i = 0; i < NITER; i++) {
        if (i == NITER - 1) CP_WAIT0(); else CP_WAIT1();
        __syncthreads();
        if (i + 2 < NITER) load_stage((i + 2) % NSTAGE, i + 2);

        uint32_t st = sbase + (uint32_t)(i % NSTAGE) * STAGE_BYTES;
        #pragma unroll
        for (int kk = 0; kk < 2; kk++) {       // two k16 steps per BK=32 stage
            uint32_t ah[4][4], bh[2][4];
            #pragma unroll
            for (int mi = 0; mi < 4; mi++) {
                int row = warpm * 64 + mi * 16 + (lane & 15);
                int c = kk * 2 + (lane >> 4);
                LDSM_X4(ah[mi][0], ah[mi][1], ah[mi][2], ah[mi][3], st + swz(row, c));
            }
            #pragma unroll
            for (int pr = 0; pr < 2; pr++) {
                int row = warpn * 32 + pr * 16 + (lane & 7) + (((lane >> 4) & 1) << 3);
                int c = kk * 2 + ((lane >> 3) & 1);
                LDSM_X4(bh[pr][0], bh[pr][1], bh[pr][2], bh[pr][3], st + 8192 + swz(row, c));
            }
            #pragma unroll
            for (int mi = 0; mi < 4; mi++)
                #pragma unroll
                for (int ni = 0; ni < 4; ni++)
                    MMA_F16(acc[mi][ni], ah[mi], bh[ni >> 1][(ni & 1) * 2], bh[ni >> 1][(ni & 1) * 2 + 1]);
        }
    }

    // ---------------- epilogue ----------------
    const int mb0 = bm + warpm * 64;
    const int nb0 = bn + warpn * 32;
    #pragma unroll
    for (int mi = 0; mi < 4; mi++) {
        #pragma unroll
        for (int r = 0; r < 2; r++) {
            int m = mb0 + mi * 16 + (lane >> 2) + r * 8;
            size_t off = (size_t)m * Dd;
            #pragma unroll
            for (int ni = 0; ni < 4; ni++) {
                int n = nb0 + ni * 8 + (lane & 3) * 2;
                float v0 = acc[mi][ni][r * 2], v1 = acc[mi][ni][r * 2 + 1];
                if (MODE == 0) {
                    float2 bv = *(const float2*)&aux1[n];
                    *(__half2*)&g_dt16[off + n] =
                        __floats2half2_rn(softplusf(v0 + bv.x), softplusf(v1 + bv.y));
                } else if (MODE == 1) {
                    float2 dt = __half22float2(*(const __half2*)&g_dt16[off + n]);
                    float2 al2 = *(const float2*)&aux2[n];
                    float2 xv = *(const float2*)&xptr[off + n];
                    float2 gv, iv;
                    gv.x = expf(dt.x * (-expf(al2.x)));
                    gv.y = expf(dt.y * (-expf(al2.y)));
                    iv.x = dt.x * v0 * xv.x;
                    iv.y = dt.y * v1 * xv.y;
                    if ((m & (Ss - 1)) == 0) {
                        int b = m / Ss;
                        float2 h0v = *(const float2*)&aux3[(size_t)b * Dd + n];
                        iv.x += gv.x * h0v.x;
                        iv.y += gv.y * h0v.y;
                    }
                    g_gi[off + n]     = __floats2half2_rn(gv.x, iv.x);
                    g_gi[off + n + 1] = __floats2half2_rn(gv.y, iv.y);
                } else {
                    float2 dp = *(const float2*)&aux1[n];
                    float2 xv = *(const float2*)&xptr[off + n];
                    float2 o;
                    o.x = v0 + dp.x * xv.x;
                    o.y = v1 + dp.y * xv.y;
                    *(float2*)&out[off + n] = o;
                }
            }
        }
    }
}

// ---------------- chunked associative scan ----------------
__global__ void scan_pass1()
{
    int idx = blockIdx.x * blockDim.x + threadIdx.x;
    int d = idx & (Dd - 1);
    int chunk = (idx / Dd) & (NCHUNK - 1);
    int b = idx / (Dd * NCHUNK);
    size_t base = ((size_t)b * Ss + (size_t)chunk * CLEN) * Dd + d;
    float a = 1.0f, h = 0.0f;
    #pragma unroll 8
    for (int t = 0; t < CLEN; t++) {
        float2 gi = __half22float2(g_gi[base + (size_t)t * Dd]);
        a *= gi.x;
        h = gi.x * h + gi.y;
    }
    g_Ac[idx] = a;
    g_Bc[idx] = h;
}

__global__ void scan_pass2()
{
    int idx = blockIdx.x * blockDim.x + threadIdx.x;   // b*D + d
    int d = idx & (Dd - 1);
    int b = idx / Dd;
    const int base = b * NCHUNK * Dd + d;

    float A0[8], B0[8], A1[8], B1[8];
    #pragma unroll
    for (int j = 0; j < 8; j++) {
        A0[j] = g_Ac[base + j * Dd];
        B0[j] = g_Bc[base + j * Dd];
    }
    float c = 0.0f;
    #pragma unroll
    for (int ch = 0; ch < 8; ch++) {
        if (ch < 7) {
            #pragma unroll
            for (int j = 0; j < 8; j++) {
                A1[j] = g_Ac[base + ((ch + 1) * 8 + j) * Dd];
                B1[j] = g_Bc[base + ((ch + 1) * 8 + j) * Dd];
            }
        }
        #pragma unroll
        for (int j = 0; j < 8; j++) {
            g_carry[base + (ch * 8 + j) * Dd] = c;
            c = A0[j] * c + B0[j];
        }
        #pragma unroll
        for (int j = 0; j < 8; j++) { A0[j] = A1[j]; B0[j] = B1[j]; }
    }
}

__global__ void scan_pass3()
{
    int idx = blockIdx.x * blockDim.x + threadIdx.x;
    int d = idx & (Dd - 1);
    int chunk = (idx / Dd) & (NCHUNK - 1);
    int b = idx / (Dd * NCHUNK);
    size_t base = ((size_t)b * Ss + (size_t)chunk * CLEN) * Dd + d;
    float h = g_carry[idx];
    #pragma unroll 8
    for (int t = 0; t < CLEN; t++) {
        size_t o = base + (size_t)t * Dd;
        float2 gi = __half22float2(g_gi[o]);
        h = gi.x * h + gi.y;
        g_h16[o] = __float2half(h);
    }
}

extern "C" void kernel_launch(void* const* d_in, const int* in_sizes, int n_in,
                              void* d_out, int out_size)
{
    const float* x     = (const float*)d_in[0];
    const float* h0    = (const float*)d_in[1];
    const float* dt_w  = (const float*)d_in[2];
    const float* dt_b  = (const float*)d_in[3];
    const float* A_log = (const float*)d_in[4];
    const float* B_w   = (const float*)d_in[5];
    const float* C_w   = (const float*)d_in[6];
    const float* Dp    = (const float*)d_in[7];
    float* out = (float*)d_out;

    cudaFuncSetAttribute(gemm_f16<0>, cudaFuncAttributeMaxDynamicSharedMemorySize, SMEM_DYN);
    cudaFuncSetAttribute(gemm_f16<1>, cudaFuncAttributeMaxDynamicSharedMemorySize, SMEM_DYN);
    cudaFuncSetAttribute(gemm_f16<2>, cudaFuncAttributeMaxDynamicSharedMemorySize, SMEM_DYN);

    conv_x<<<((size_t)Mm * Dd) / 2048, 256>>>(x);
    conv_w3<<<dim3(((size_t)Dd * Dd) / 2048, 3), 256>>>(dt_w, B_w, C_w);

    dim3 grid(Dd / BN, Mm / BM);   // (8, 128)
    dim3 blk(256);

    gemm_f16<0><<<grid, blk, SMEM_DYN>>>(nullptr, dt_b, nullptr, nullptr, nullptr);
    gemm_f16<1><<<grid, blk, SMEM_DYN>>>(nullptr, nullptr, A_log, h0, x);
    scan_pass1<<<(Bb * NCHUNK * Dd) / 256, 256>>>();
    scan_pass2<<<(Bb * Dd) / 256, 256>>>();
    scan_pass3<<<(Bb * NCHUNK * Dd) / 256, 256>>>();
    gemm_f16<2><<<grid, blk, SMEM_DYN>>>(out, Dp, nullptr, nullptr, x);
}